// round 14
// baseline (speedup 1.0000x reference)
#include <cuda_runtime.h>
#include <cuda_fp16.h>
#include <cstdint>
#include <math.h>

#define Bb 2
#define Cc 1024
#define Tt 2048
#define Hh 16
#define Dd 64
/* exp2-domain scale: 1/sqrt(64) * log2(e) */
#define Q2SCALE 0.18033688011112042f

typedef __half f16;

// ---------------- scratch (device globals: allocation-free) ----------------
__device__ float g_maskf[Bb * Tt];
__device__ float g_maskbias[Bb * Tt];
__device__ f16 g_Wq[Cc * Cc], g_Wk[Cc * Cc], g_Wv[Cc * Cc], g_Wp[Cc * Cc];
__device__ f16 g_Xth[(size_t)Bb * Tt * Cc], g_Xtl[(size_t)Bb * Tt * Cc];
__device__ f16 g_Q[(size_t)Bb * Hh * Tt * Dd];
__device__ f16 g_Kh[(size_t)Bb * Hh * Tt * Dd], g_Kl[(size_t)Bb * Hh * Tt * Dd];
__device__ f16 g_Vh[(size_t)Bb * Hh * Tt * Dd], g_Vl[(size_t)Bb * Hh * Tt * Dd];
__device__ f16 g_Cth[(size_t)Bb * Tt * Cc], g_Ctl[(size_t)Bb * Tt * Cc];

// ======================= helpers =======================
__device__ __forceinline__ uint32_t smem_to_u32(const void* p) {
    uint32_t a;
    asm("{ .reg .u64 t; cvta.to.shared.u64 t, %1; cvt.u32.u64 %0, t; }"
        : "=r"(a) : "l"(p));
    return a;
}
__device__ __forceinline__ float ex2(float x) {
    float r;
    asm("ex2.approx.f32 %0, %1;" : "=f"(r) : "f"(x));
    return r;
}
#define CP_ASYNC16(saddr, gptr) \
    asm volatile("cp.async.cg.shared.global [%0], [%1], 16;" \
        :: "r"(saddr), "l"(gptr) : "memory")
#define CP_COMMIT() asm volatile("cp.async.commit_group;" ::: "memory")
#define CP_WAIT(N)  asm volatile("cp.async.wait_group %0;" :: "n"(N) : "memory")
#define LDMATRIX_X4(r0, r1, r2, r3, addr) \
    asm volatile("ldmatrix.sync.aligned.m8n8.x4.shared.b16 {%0,%1,%2,%3}, [%4];" \
        : "=r"(r0), "=r"(r1), "=r"(r2), "=r"(r3) : "r"(addr))
#define LDMATRIX_X4T(r0, r1, r2, r3, addr) \
    asm volatile("ldmatrix.sync.aligned.m8n8.x4.trans.shared.b16 {%0,%1,%2,%3}, [%4];" \
        : "=r"(r0), "=r"(r1), "=r"(r2), "=r"(r3) : "r"(addr))
#define MMA_F16(c, a, b) \
    asm volatile("mma.sync.aligned.m16n8k16.row.col.f32.f16.f16.f32 " \
        "{%0,%1,%2,%3}, {%4,%5,%6,%7}, {%8,%9}, {%0,%1,%2,%3};" \
        : "+f"((c)[0]), "+f"((c)[1]), "+f"((c)[2]), "+f"((c)[3]) \
        : "r"((a)[0]), "r"((a)[1]), "r"((a)[2]), "r"((a)[3]), \
          "r"((b)[0]), "r"((b)[1]))

__device__ __forceinline__ uint32_t pack_h2(float x, float y) {
    __half2 t = __floats2half2_rn(x, y);
    return *(uint32_t*)&t;
}

// ---------------- mask normalization ----------------
__global__ void mask_convert_kernel(const void* __restrict__ mraw) {
    const int tid = threadIdx.x;
    bool isf = true, isi = true;
    const float* f = (const float*)mraw;
    const int* w = (const int*)mraw;
    for (int i = tid; i < Bb * Tt / 4; i += 256) {
        float v = f[i];
        if (!(v == 0.0f || v == 1.0f)) isf = false;
        int iv = w[i];
        if (!(iv == 0 || iv == 1)) isi = false;
    }
    int allf = __syncthreads_and(isf ? 1 : 0);
    int alli = __syncthreads_and(isi ? 1 : 0);
    int fmt = allf ? 0 : (alli ? 1 : 2);
    for (int i = tid; i < Bb * Tt; i += 256) {
        float v;
        if (fmt == 0)      v = ((const float*)mraw)[i];
        else if (fmt == 1) v = (float)((const int*)mraw)[i];
        else               v = (float)((const unsigned char*)mraw)[i];
        bool on = (v != 0.0f);
        g_maskf[i] = on ? 1.0f : 0.0f;
        g_maskbias[i] = on ? 0.0f : -1e30f;
    }
}

// ---------------- conversions ----------------
__global__ void convw4_kernel(
    const float* __restrict__ s0, const float* __restrict__ s1,
    const float* __restrict__ s2, const float* __restrict__ s3)
{
    const float* s;
    f16* h;
    switch (blockIdx.y) {
        case 0:  s = s0; h = g_Wq; break;
        case 1:  s = s1; h = g_Wk; break;
        case 2:  s = s2; h = g_Wv; break;
        default: s = s3; h = g_Wp; break;
    }
    int i = (blockIdx.x * 256 + threadIdx.x) * 4;
    float4 v = *(const float4*)(s + i);
    uint2 ho;
    ho.x = pack_h2(v.x, v.y);
    ho.y = pack_h2(v.z, v.w);
    *(uint2*)(h + i) = ho;
}

// src [b][C][T] f32 -> dst [b][T][C] fp16 hi/lo (exact split)
__global__ void convT_kernel(const float* __restrict__ src,
                             f16* __restrict__ dh, f16* __restrict__ dl) {
    __shared__ float tile[32][33];
    const int b = blockIdx.z;
    const int t0 = blockIdx.x * 32;
    const int c0 = blockIdx.y * 32;
    const float* s = src + (size_t)b * Cc * Tt;
    f16* oh = dh + (size_t)b * Tt * Cc;
    f16* ol = dl + (size_t)b * Tt * Cc;
    const int tx = threadIdx.x;
    const int ty = threadIdx.y;
#pragma unroll
    for (int i = ty; i < 32; i += 8)
        tile[i][tx] = s[(size_t)(c0 + i) * Tt + t0 + tx];
    __syncthreads();
#pragma unroll
    for (int i = ty; i < 32; i += 8) {
        float v = tile[tx][i];
        f16 hi = __float2half_rn(v);
        size_t idx = (size_t)(t0 + i) * Cc + c0 + tx;
        oh[idx] = hi;
        ol[idx] = __float2half_rn(v - __half2float(hi));
    }
}

// ---------------- fp16 2-term projection GEMMs ----------------
// A = W plain fp16 [o][c]; B = X^T split hi/lo fp16 [t][c].
// CTA 128x128, 8 warps of 64x32, BK=32, 3-stage cp.async, 2 CTA/SM.
#define BM 128
#define BN 128
#define BK 32
#define ROWB 80
#define T_TILE (128 * ROWB)        /* 10240 */
#define STAGE_B (3 * T_TILE)       /* 30720 */
#define PJ_SMEM (3 * STAGE_B)      /* 92160 -> x2 CTA = 184320 */

#define PROJ_BODY(AP, BhP, BlP)                                                \
    float acc[4][4][4];                                                        \
    _Pragma("unroll")                                                          \
    for (int mi = 0; mi < 4; mi++)                                             \
        _Pragma("unroll")                                                      \
        for (int ni = 0; ni < 4; ni++)                                         \
            _Pragma("unroll")                                                  \
            for (int e = 0; e < 4; e++) acc[mi][ni][e] = 0.0f;                 \
    const int lr = tid >> 2;                                                   \
    const int lch = tid & 3;                                                   \
    const int rowA = (((lane >> 3) & 1) << 3) + (lane & 7);                    \
    const int colA = (lane >> 4) << 3;                                         \
    const int rowB2 = ((lane >> 4) << 3) + (lane & 7);                         \
    const int colB2 = ((lane >> 3) & 1) << 3;                                  \
    auto prefetch = [&](int k0, uint32_t s0) {                                 \
        int ge = k0 + lch * 8;                                                 \
        _Pragma("unroll")                                                      \
        for (int j = 0; j < 2; j++) {                                          \
            int r = lr + j * 64;                                               \
            uint32_t so = (uint32_t)(r * ROWB + lch * 16);                     \
            CP_ASYNC16(s0 + so,              AP + (size_t)(row0 + r) * Cc + ge);  \
            CP_ASYNC16(s0 + T_TILE + so,     BhP + (size_t)(col0 + r) * Cc + ge); \
            CP_ASYNC16(s0 + 2 * T_TILE + so, BlP + (size_t)(col0 + r) * Cc + ge); \
        }                                                                      \
    };                                                                         \
    prefetch(0, sb);                                                           \
    CP_COMMIT();                                                               \
    prefetch(BK, sb + STAGE_B);                                                \
    CP_COMMIT();                                                               \
    int stage = 0;                                                             \
    const int NKst = Cc / BK;                                                  \
    _Pragma("unroll 1")                                                        \
    for (int ks = 0; ks < NKst; ks++) {                                        \
        if (ks + 1 < NKst) { CP_WAIT(1); } else { CP_WAIT(0); }                \
        __syncthreads();                                                       \
        if (ks + 2 < NKst) {                                                   \
            int ns = stage + 2;                                                \
            if (ns >= 3) ns -= 3;                                              \
            prefetch((ks + 2) * BK, sb + ns * STAGE_B);                        \
            CP_COMMIT();                                                       \
        }                                                                      \
        const uint32_t sA = sb + stage * STAGE_B;                              \
        const uint32_t sBh = sA + T_TILE;                                      \
        const uint32_t sBl = sA + 2 * T_TILE;                                  \
        _Pragma("unroll")                                                      \
        for (int kk = 0; kk < 32; kk += 16) {                                  \
            uint32_t a_f[4][4];                                                \
            _Pragma("unroll")                                                  \
            for (int mi = 0; mi < 4; mi++) {                                   \
                uint32_t off = (uint32_t)((wm + mi * 16 + rowA) * ROWB +       \
                                          (kk + colA) * 2);                    \
                LDMATRIX_X4(a_f[mi][0], a_f[mi][1], a_f[mi][2], a_f[mi][3],    \
                            sA + off);                                         \
            }                                                                  \
            uint32_t b_h[4][2], b_l[4][2];                                     \
            _Pragma("unroll")                                                  \
            for (int pr = 0; pr < 2; pr++) {                                   \
                uint32_t off = (uint32_t)((wn + pr * 16 + rowB2) * ROWB +      \
                                          (kk + colB2) * 2);                   \
                LDMATRIX_X4(b_h[2 * pr][0], b_h[2 * pr][1],                    \
                            b_h[2 * pr + 1][0], b_h[2 * pr + 1][1], sBh + off);\
                LDMATRIX_X4(b_l[2 * pr][0], b_l[2 * pr][1],                    \
                            b_l[2 * pr + 1][0], b_l[2 * pr + 1][1], sBl + off);\
            }                                                                  \
            _Pragma("unroll")                                                  \
            for (int mi = 0; mi < 4; mi++)                                     \
                _Pragma("unroll")                                              \
                for (int ni = 0; ni < 4; ni++)                                 \
                    MMA_F16(acc[mi][ni], a_f[mi], b_h[ni]);                    \
            _Pragma("unroll")                                                  \
            for (int mi = 0; mi < 4; mi++)                                     \
                _Pragma("unroll")                                              \
                for (int ni = 0; ni < 4; ni++)                                 \
                    MMA_F16(acc[mi][ni], a_f[mi], b_l[ni]);                    \
        }                                                                      \
        stage++;                                                               \
        if (stage == 3) stage = 0;                                             \
    }

// Merged Q/K/V projection. grid = (Tt/BN, Cc/BM, 6); z = mat*2 + batch.
__global__ void __launch_bounds__(256, 2) qkv_mma_kernel(
    const float* __restrict__ bq, const float* __restrict__ bk,
    const float* __restrict__ bv)
{
    extern __shared__ char smem[];
    const uint32_t sb = smem_to_u32(smem);
    const int tid = threadIdx.x;
    const int wid = tid >> 5;
    const int lane = tid & 31;
    const int z = blockIdx.z;
    const int b = z & 1;
    const int mat = z >> 1;
    const int row0 = blockIdx.y * BM;
    const int col0 = blockIdx.x * BN;

    const f16* A;
    const float* bias;
    f16 *oh, *ol;
    bool domask;
    if (mat == 0)      { A = g_Wq; bias = bq; oh = g_Q;  ol = nullptr; domask = false; }
    else if (mat == 1) { A = g_Wk; bias = bk; oh = g_Kh; ol = g_Kl; domask = false; }
    else               { A = g_Wv; bias = bv; oh = g_Vh; ol = g_Vl; domask = true; }
    const f16* Bh = g_Xth + (size_t)b * Tt * Cc;
    const f16* Bl = g_Xtl + (size_t)b * Tt * Cc;

    const int wm = (wid >> 2) * 64;
    const int wn = (wid & 3) * 32;

    PROJ_BODY(A, Bh, Bl)

    const int g = lane >> 2;
    const int tig = lane & 3;
#pragma unroll
    for (int mi = 0; mi < 4; mi++) {
#pragma unroll
        for (int part = 0; part < 2; part++) {
            const int o = row0 + wm + mi * 16 + g + part * 8;
            const float bo = bias[o];
#pragma unroll
            for (int ni = 0; ni < 4; ni++) {
#pragma unroll
                for (int e = 0; e < 2; e++) {
                    const int t = col0 + wn + ni * 8 + tig * 2 + e;
                    float v = acc[mi][ni][part * 2 + e] + bo;
                    size_t idx =
                        (((size_t)b * Hh + (o >> 6)) * Tt + t) * Dd + (o & 63);
                    if (mat == 0) {
                        oh[idx] = __float2half_rn(v * Q2SCALE);
                    } else {
                        if (domask) v *= g_maskf[b * Tt + t];
                        f16 hi = __float2half_rn(v);
                        oh[idx] = hi;
                        ol[idx] = __float2half_rn(v - __half2float(hi));
                    }
                }
            }
        }
    }
}

// Output projection: f32 out * mask. grid = (Tt/BN, Cc/BM, Bb).
__global__ void __launch_bounds__(256, 2) projp_mma_kernel(
    const float* __restrict__ bp, float* __restrict__ outf)
{
    extern __shared__ char smem[];
    const uint32_t sb = smem_to_u32(smem);
    const int tid = threadIdx.x;
    const int wid = tid >> 5;
    const int lane = tid & 31;
    const int b = blockIdx.z;
    const int row0 = blockIdx.y * BM;
    const int col0 = blockIdx.x * BN;

    const f16* A = g_Wp;
    const f16* Bh = g_Cth + (size_t)b * Tt * Cc;
    const f16* Bl = g_Ctl + (size_t)b * Tt * Cc;

    const int wm = (wid >> 2) * 64;
    const int wn = (wid & 3) * 32;

    PROJ_BODY(A, Bh, Bl)

    const int g = lane >> 2;
    const int tig = lane & 3;
#pragma unroll
    for (int mi = 0; mi < 4; mi++) {
#pragma unroll
        for (int part = 0; part < 2; part++) {
            const int o = row0 + wm + mi * 16 + g + part * 8;
            const float bo = bp[o];
#pragma unroll
            for (int ni = 0; ni < 4; ni++) {
#pragma unroll
                for (int e = 0; e < 2; e++) {
                    const int t = col0 + wn + ni * 8 + tig * 2 + e;
                    float v = acc[mi][ni][part * 2 + e] + bo;
                    outf[((size_t)b * Cc + o) * Tt + t] = v * g_maskf[b * Tt + t];
                }
            }
        }
    }
}

// ---------------- fp16 2-term flash attention, 3-stage pipeline ----------------
// S = Q_f16 (Kh+Kl); O = P_f16 (Vh+Vl). 128 thr / 128 q-rows, m32 warps,
// 32-key tiles, 3-stage cp.async ring with CP_WAIT(1), ex2 softmax.
#define KST 72
#define AT_TILE (32 * KST * 2)             /* 4608 B per array */
#define AT_STAGE (4 * AT_TILE + 128)       /* 18560 B */
#define AT_SMEM (3 * AT_STAGE)             /* 55680 B -> x2 CTA = 111360 */

__global__ void __launch_bounds__(128, 2) attn_mma_kernel()
{
    extern __shared__ char dynsm[];
    const uint32_t sbase = smem_to_u32(dynsm);

    const int tid = threadIdx.x;
    const int wid = tid >> 5;
    const int lane = tid & 31;
    const int g = lane >> 2;
    const int tig = lane & 3;
    const int bh = blockIdx.y;
    const int b = bh >> 4;
    const int q0 = blockIdx.x * 128;
    const size_t base = (size_t)bh * Tt * Dd;

    const f16* Q = g_Q;
    const f16* Kh = g_Kh; const f16* Kl = g_Kl;
    const f16* Vh = g_Vh; const f16* Vl = g_Vl;
    f16* Ch = g_Cth; f16* Cl = g_Ctl;

    const int rowB = ((lane >> 4) << 3) + (lane & 7);
    const int colB = ((lane >> 3) & 1) << 3;
    const int vrow = (lane & 7) + ((lane >> 3) & 1) * 8;
    const int vcol = (lane >> 4) << 3;

    const int ldrow = tid >> 2;
    const int ldch = tid & 3;

    auto prefetch = [&](int kt, uint32_t st) {
        const char* gk  = (const char*)(Kh + base + (size_t)(kt + ldrow) * Dd);
        const char* gkl = (const char*)(Kl + base + (size_t)(kt + ldrow) * Dd);
        const char* gv  = (const char*)(Vh + base + (size_t)(kt + ldrow) * Dd);
        const char* gvl = (const char*)(Vl + base + (size_t)(kt + ldrow) * Dd);
        uint32_t so = st + (uint32_t)(ldrow * (KST * 2));
#pragma unroll
        for (int cc = 0; cc < 2; cc++) {
            uint32_t off = (uint32_t)((ldch + cc * 4) * 16);
            CP_ASYNC16(so + off,                gk + off);
            CP_ASYNC16(so + AT_TILE + off,      gkl + off);
            CP_ASYNC16(so + 2 * AT_TILE + off,  gv + off);
            CP_ASYNC16(so + 3 * AT_TILE + off,  gvl + off);
        }
        if (tid < 8) {
            const char* gm = (const char*)(g_maskbias + b * Tt + kt) + tid * 16;
            CP_ASYNC16(st + 4 * AT_TILE + tid * 16, gm);
        }
    };

    uint32_t qf[2][4][4];
#pragma unroll
    for (int mi = 0; mi < 2; mi++) {
        const size_t r0 = base + (size_t)(q0 + wid * 32 + mi * 16 + g) * Dd;
        const size_t r1 = r0 + 8 * Dd;
#pragma unroll
        for (int c = 0; c < 4; c++) {
            int k0 = c * 16 + tig * 2;
            qf[mi][c][0] = *(const uint32_t*)(Q + r0 + k0);
            qf[mi][c][1] = *(const uint32_t*)(Q + r1 + k0);
            qf[mi][c][2] = *(const uint32_t*)(Q + r0 + k0 + 8);
            qf[mi][c][3] = *(const uint32_t*)(Q + r1 + k0 + 8);
        }
    }

    float oacc[2][8][4];
#pragma unroll
    for (int mi = 0; mi < 2; mi++)
#pragma unroll
        for (int j = 0; j < 8; j++)
#pragma unroll
            for (int e = 0; e < 4; e++) oacc[mi][j][e] = 0.0f;
    float mrow[2][2], lrow[2][2];
#pragma unroll
    for (int mi = 0; mi < 2; mi++) {
        mrow[mi][0] = -3.0e38f; mrow[mi][1] = -3.0e38f;
        lrow[mi][0] = 0.0f;     lrow[mi][1] = 0.0f;
    }

    prefetch(0, sbase);
    CP_COMMIT();
    prefetch(32, sbase + AT_STAGE);
    CP_COMMIT();

    int stage = 0;
    const int NT = Tt / 32;
#pragma unroll 1
    for (int it = 0; it < NT; it++) {
        if (it + 1 < NT) { CP_WAIT(1); } else { CP_WAIT(0); }
        __syncthreads();
        if (it + 2 < NT) {
            int ns = stage + 2;
            if (ns >= 3) ns -= 3;
            prefetch((it + 2) * 32, sbase + ns * AT_STAGE);
            CP_COMMIT();
        }

        const uint32_t aKh = sbase + stage * AT_STAGE;
        const uint32_t aKl = aKh + AT_TILE;
        const uint32_t aVh = aKh + 2 * AT_TILE;
        const uint32_t aVl = aKh + 3 * AT_TILE;
        const float* msk = (const float*)(dynsm + stage * AT_STAGE + 4 * AT_TILE);

        float sacc[2][4][4];
#pragma unroll
        for (int mi = 0; mi < 2; mi++)
#pragma unroll
            for (int j = 0; j < 4; j++)
#pragma unroll
                for (int e = 0; e < 4; e++) sacc[mi][j][e] = 0.0f;

#pragma unroll
        for (int c = 0; c < 4; c++) {
            uint32_t kbh[4][2], kbl[4][2];
#pragma unroll
            for (int pr = 0; pr < 2; pr++) {
                uint32_t off = (uint32_t)(((pr * 16 + rowB) * KST +
                                           c * 16 + colB) * 2);
                LDMATRIX_X4(kbh[2 * pr][0], kbh[2 * pr][1],
                            kbh[2 * pr + 1][0], kbh[2 * pr + 1][1], aKh + off);
                LDMATRIX_X4(kbl[2 * pr][0], kbl[2 * pr][1],
                            kbl[2 * pr + 1][0], kbl[2 * pr + 1][1], aKl + off);
            }
#pragma unroll
            for (int mi = 0; mi < 2; mi++)
#pragma unroll
                for (int j = 0; j < 4; j++)
                    MMA_F16(sacc[mi][j], qf[mi][c], kbh[j]);
#pragma unroll
            for (int mi = 0; mi < 2; mi++)
#pragma unroll
                for (int j = 0; j < 4; j++)
                    MMA_F16(sacc[mi][j], qf[mi][c], kbl[j]);
        }

        float al[2][2];
#pragma unroll
        for (int mi = 0; mi < 2; mi++) {
            float mx0 = -3.0e38f, mx1 = -3.0e38f;
#pragma unroll
            for (int j = 0; j < 4; j++) {
                float mb0 = msk[j * 8 + tig * 2];
                float mb1 = msk[j * 8 + tig * 2 + 1];
                float s0 = sacc[mi][j][0] + mb0;
                float s1 = sacc[mi][j][1] + mb1;
                float s2 = sacc[mi][j][2] + mb0;
                float s3 = sacc[mi][j][3] + mb1;
                sacc[mi][j][0] = s0; sacc[mi][j][1] = s1;
                sacc[mi][j][2] = s2; sacc[mi][j][3] = s3;
                mx0 = fmaxf(mx0, fmaxf(s0, s1));
                mx1 = fmaxf(mx1, fmaxf(s2, s3));
            }
            mx0 = fmaxf(mx0, __shfl_xor_sync(0xffffffffu, mx0, 1));
            mx0 = fmaxf(mx0, __shfl_xor_sync(0xffffffffu, mx0, 2));
            mx1 = fmaxf(mx1, __shfl_xor_sync(0xffffffffu, mx1, 1));
            mx1 = fmaxf(mx1, __shfl_xor_sync(0xffffffffu, mx1, 2));
            float mn0 = fmaxf(mrow[mi][0], mx0);
            float mn1 = fmaxf(mrow[mi][1], mx1);
            float sum0 = 0.0f, sum1 = 0.0f;
#pragma unroll
            for (int j = 0; j < 4; j++) {
                float p0 = ex2(sacc[mi][j][0] - mn0);
                float p1 = ex2(sacc[mi][j][1] - mn0);
                float p2 = ex2(sacc[mi][j][2] - mn1);
                float p3 = ex2(sacc[mi][j][3] - mn1);
                sacc[mi][j][0] = p0; sacc[mi][j][1] = p1;
                sacc[mi][j][2] = p2; sacc[mi][j][3] = p3;
                sum0 += p0 + p1;
                sum1 += p2 + p3;
            }
            sum0 += __shfl_xor_sync(0xffffffffu, sum0, 1);
            sum0 += __shfl_xor_sync(0xffffffffu, sum0, 2);
            sum1 += __shfl_xor_sync(0xffffffffu, sum1, 1);
            sum1 += __shfl_xor_sync(0xffffffffu, sum1, 2);
            float a0 = ex2(mrow[mi][0] - mn0);
            float a1 = ex2(mrow[mi][1] - mn1);
            lrow[mi][0] = lrow[mi][0] * a0 + sum0;
            lrow[mi][1] = lrow[mi][1] * a1 + sum1;
            mrow[mi][0] = mn0;
            mrow[mi][1] = mn1;
            al[mi][0] = a0;
            al[mi][1] = a1;
        }
#pragma unroll
        for (int mi = 0; mi < 2; mi++)
#pragma unroll
            for (int j = 0; j < 8; j++) {
                oacc[mi][j][0] *= al[mi][0]; oacc[mi][j][1] *= al[mi][0];
                oacc[mi][j][2] *= al[mi][1]; oacc[mi][j][3] *= al[mi][1];
            }

#pragma unroll
        for (int kc = 0; kc < 2; kc++) {
            uint32_t vbh[8][2], vbl[8][2];
#pragma unroll
            for (int ng = 0; ng < 4; ng++) {
                uint32_t off = (uint32_t)(((kc * 16 + vrow) * KST +
                                           ng * 16 + vcol) * 2);
                LDMATRIX_X4T(vbh[2 * ng][0], vbh[2 * ng][1],
                             vbh[2 * ng + 1][0], vbh[2 * ng + 1][1], aVh + off);
                LDMATRIX_X4T(vbl[2 * ng][0], vbl[2 * ng][1],
                             vbl[2 * ng + 1][0], vbl[2 * ng + 1][1], aVl + off);
            }
            uint32_t paf[2][4];
#pragma unroll
            for (int mi = 0; mi < 2; mi++) {
                paf[mi][0] = pack_h2(sacc[mi][2 * kc][0], sacc[mi][2 * kc][1]);
                paf[mi][1] = pack_h2(sacc[mi][2 * kc][2], sacc[mi][2 * kc][3]);
                paf[mi][2] = pack_h2(sacc[mi][2 * kc + 1][0], sacc[mi][2 * kc + 1][1]);
                paf[mi][3] = pack_h2(sacc[mi][2 * kc + 1][2], sacc[mi][2 * kc + 1][3]);
            }
#pragma unroll
            for (int mi = 0; mi < 2; mi++)
#pragma unroll
                for (int j = 0; j < 8; j++)
                    MMA_F16(oacc[mi][j], paf[mi], vbh[j]);
#pragma unroll
            for (int mi = 0; mi < 2; mi++)
#pragma unroll
                for (int j = 0; j < 8; j++)
                    MMA_F16(oacc[mi][j], paf[mi], vbl[j]);
        }
        stage++;
        if (stage == 3) stage = 0;
    }

    // ---- epilogue: ctx[b][t][c] fp16 hi/lo ----
    const int cb = (bh & 15) * 64;
#pragma unroll
    for (int mi = 0; mi < 2; mi++) {
        const float inv0 = 1.0f / lrow[mi][0];
        const float inv1 = 1.0f / lrow[mi][1];
        const int t0 = q0 + wid * 32 + mi * 16 + g;
        const size_t o0 = ((size_t)b * Tt + t0) * Cc + cb;
        const size_t o1 = o0 + 8 * Cc;
#pragma unroll
        for (int j = 0; j < 8; j++) {
            int cc = j * 8 + tig * 2;
            float v0 = oacc[mi][j][0] * inv0, v1 = oacc[mi][j][1] * inv0;
            float v2 = oacc[mi][j][2] * inv1, v3 = oacc[mi][j][3] * inv1;
            float h0 = __half2float(__float2half_rn(v0));
            float h1 = __half2float(__float2half_rn(v1));
            float h2 = __half2float(__float2half_rn(v2));
            float h3 = __half2float(__float2half_rn(v3));
            *(uint32_t*)(Ch + o0 + cc) = pack_h2(v0, v1);
            *(uint32_t*)(Cl + o0 + cc) = pack_h2(v0 - h0, v1 - h1);
            *(uint32_t*)(Ch + o1 + cc) = pack_h2(v2, v3);
            *(uint32_t*)(Cl + o1 + cc) = pack_h2(v2 - h2, v3 - h3);
        }
    }
}

// ---------------- mask echo (second tuple output) ----------------
__global__ void mask_out_kernel(float* __restrict__ out) {
    int i = blockIdx.x * blockDim.x + threadIdx.x;
    if (i < Bb * Tt) out[i] = g_maskf[i];
}

// ---------------- launch ----------------
extern "C" void kernel_launch(void* const* d_in, const int* in_sizes, int n_in,
                              void* d_out, int out_size)
{
    const float* x  = (const float*)d_in[0];
    const void*  mk = d_in[1];
    const float* Wq = (const float*)d_in[2];
    const float* bq = (const float*)d_in[3];
    const float* Wk = (const float*)d_in[4];
    const float* bk = (const float*)d_in[5];
    const float* Wv = (const float*)d_in[6];
    const float* bv = (const float*)d_in[7];
    const float* Wp = (const float*)d_in[8];
    const float* bp = (const float*)d_in[9];
    float* out = (float*)d_out;

    f16 *xth, *xtl;
    cudaGetSymbolAddress((void**)&xth, g_Xth);
    cudaGetSymbolAddress((void**)&xtl, g_Xtl);

    cudaFuncSetAttribute(qkv_mma_kernel,
                         cudaFuncAttributeMaxDynamicSharedMemorySize, PJ_SMEM);
    cudaFuncSetAttribute(projp_mma_kernel,
                         cudaFuncAttributeMaxDynamicSharedMemorySize, PJ_SMEM);
    cudaFuncSetAttribute(attn_mma_kernel,
                         cudaFuncAttributeMaxDynamicSharedMemorySize, AT_SMEM);

    mask_convert_kernel<<<1, 256>>>(mk);

    convw4_kernel<<<dim3(Cc * Cc / 1024, 4), 256>>>(Wq, Wk, Wv, Wp);
    convT_kernel<<<dim3(Tt / 32, Cc / 32, Bb), dim3(32, 8)>>>(x, xth, xtl);

    qkv_mma_kernel<<<dim3(Tt / BN, Cc / BM, 6), 256, PJ_SMEM>>>(bq, bk, bv);

    attn_mma_kernel<<<dim3(Tt / 128, Bb * Hh), 128, AT_SMEM>>>();

    projp_mma_kernel<<<dim3(Tt / BN, Cc / BM, Bb), 256, PJ_SMEM>>>(bp, out);

    if (out_size >= Bb * Cc * Tt + Bb * Tt) {
        mask_out_kernel<<<(Bb * Tt + 255) / 256, 256>>>(out + (size_t)Bb * Cc * Tt);
    }
}

// round 15
// speedup vs baseline: 1.2237x; 1.2237x over previous
#include <cuda_runtime.h>
#include <cuda_fp16.h>
#include <cstdint>
#include <math.h>

#define Bb 2
#define Cc 1024
#define Tt 2048
#define Hh 16
#define Dd 64
/* exp2-domain scale: 1/sqrt(64) * log2(e) */
#define Q2SCALE 0.18033688011112042f

typedef __half f16;

// ---------------- scratch (device globals: allocation-free) ----------------
__device__ float g_maskf[Bb * Tt];
__device__ float g_maskbias[Bb * Tt];
__device__ f16 g_Wq[Cc * Cc], g_Wk[Cc * Cc], g_Wv[Cc * Cc], g_Wp[Cc * Cc];
__device__ f16 g_Xth[(size_t)Bb * Tt * Cc], g_Xtl[(size_t)Bb * Tt * Cc];
__device__ f16 g_Q[(size_t)Bb * Hh * Tt * Dd];
__device__ f16 g_K[(size_t)Bb * Hh * Tt * Dd];
__device__ f16 g_V[(size_t)Bb * Hh * Tt * Dd];
__device__ f16 g_Cth[(size_t)Bb * Tt * Cc], g_Ctl[(size_t)Bb * Tt * Cc];

// ======================= helpers =======================
__device__ __forceinline__ uint32_t smem_to_u32(const void* p) {
    uint32_t a;
    asm("{ .reg .u64 t; cvta.to.shared.u64 t, %1; cvt.u32.u64 %0, t; }"
        : "=r"(a) : "l"(p));
    return a;
}
__device__ __forceinline__ float ex2(float x) {
    float r;
    asm("ex2.approx.f32 %0, %1;" : "=f"(r) : "f"(x));
    return r;
}
#define CP_ASYNC16(saddr, gptr) \
    asm volatile("cp.async.cg.shared.global [%0], [%1], 16;" \
        :: "r"(saddr), "l"(gptr) : "memory")
#define CP_COMMIT() asm volatile("cp.async.commit_group;" ::: "memory")
#define CP_WAIT(N)  asm volatile("cp.async.wait_group %0;" :: "n"(N) : "memory")
#define LDMATRIX_X4(r0, r1, r2, r3, addr) \
    asm volatile("ldmatrix.sync.aligned.m8n8.x4.shared.b16 {%0,%1,%2,%3}, [%4];" \
        : "=r"(r0), "=r"(r1), "=r"(r2), "=r"(r3) : "r"(addr))
#define LDMATRIX_X4T(r0, r1, r2, r3, addr) \
    asm volatile("ldmatrix.sync.aligned.m8n8.x4.trans.shared.b16 {%0,%1,%2,%3}, [%4];" \
        : "=r"(r0), "=r"(r1), "=r"(r2), "=r"(r3) : "r"(addr))
#define MMA_F16(c, a, b) \
    asm volatile("mma.sync.aligned.m16n8k16.row.col.f32.f16.f16.f32 " \
        "{%0,%1,%2,%3}, {%4,%5,%6,%7}, {%8,%9}, {%0,%1,%2,%3};" \
        : "+f"((c)[0]), "+f"((c)[1]), "+f"((c)[2]), "+f"((c)[3]) \
        : "r"((a)[0]), "r"((a)[1]), "r"((a)[2]), "r"((a)[3]), \
          "r"((b)[0]), "r"((b)[1]))

__device__ __forceinline__ uint32_t pack_h2(float x, float y) {
    __half2 t = __floats2half2_rn(x, y);
    return *(uint32_t*)&t;
}

// ---------------- mask normalization ----------------
__global__ void mask_convert_kernel(const void* __restrict__ mraw) {
    const int tid = threadIdx.x;
    bool isf = true, isi = true;
    const float* f = (const float*)mraw;
    const int* w = (const int*)mraw;
    for (int i = tid; i < Bb * Tt / 4; i += 256) {
        float v = f[i];
        if (!(v == 0.0f || v == 1.0f)) isf = false;
        int iv = w[i];
        if (!(iv == 0 || iv == 1)) isi = false;
    }
    int allf = __syncthreads_and(isf ? 1 : 0);
    int alli = __syncthreads_and(isi ? 1 : 0);
    int fmt = allf ? 0 : (alli ? 1 : 2);
    for (int i = tid; i < Bb * Tt; i += 256) {
        float v;
        if (fmt == 0)      v = ((const float*)mraw)[i];
        else if (fmt == 1) v = (float)((const int*)mraw)[i];
        else               v = (float)((const unsigned char*)mraw)[i];
        bool on = (v != 0.0f);
        g_maskf[i] = on ? 1.0f : 0.0f;
        g_maskbias[i] = on ? 0.0f : -1e30f;
    }
}

// ---------------- conversions ----------------
__global__ void convw4_kernel(
    const float* __restrict__ s0, const float* __restrict__ s1,
    const float* __restrict__ s2, const float* __restrict__ s3)
{
    const float* s;
    f16* h;
    switch (blockIdx.y) {
        case 0:  s = s0; h = g_Wq; break;
        case 1:  s = s1; h = g_Wk; break;
        case 2:  s = s2; h = g_Wv; break;
        default: s = s3; h = g_Wp; break;
    }
    int i = (blockIdx.x * 256 + threadIdx.x) * 4;
    float4 v = *(const float4*)(s + i);
    uint2 ho;
    ho.x = pack_h2(v.x, v.y);
    ho.y = pack_h2(v.z, v.w);
    *(uint2*)(h + i) = ho;
}

// src [b][C][T] f32 -> dst [b][T][C] fp16 hi/lo (exact split)
__global__ void convT_kernel(const float* __restrict__ src,
                             f16* __restrict__ dh, f16* __restrict__ dl) {
    __shared__ float tile[32][33];
    const int b = blockIdx.z;
    const int t0 = blockIdx.x * 32;
    const int c0 = blockIdx.y * 32;
    const float* s = src + (size_t)b * Cc * Tt;
    f16* oh = dh + (size_t)b * Tt * Cc;
    f16* ol = dl + (size_t)b * Tt * Cc;
    const int tx = threadIdx.x;
    const int ty = threadIdx.y;
#pragma unroll
    for (int i = ty; i < 32; i += 8)
        tile[i][tx] = s[(size_t)(c0 + i) * Tt + t0 + tx];
    __syncthreads();
#pragma unroll
    for (int i = ty; i < 32; i += 8) {
        float v = tile[tx][i];
        f16 hi = __float2half_rn(v);
        size_t idx = (size_t)(t0 + i) * Cc + c0 + tx;
        oh[idx] = hi;
        ol[idx] = __float2half_rn(v - __half2float(hi));
    }
}

// ---------------- fp16 2-term projection GEMMs ----------------
// A = W plain fp16 [o][c]; B = X^T split hi/lo fp16 [t][c].
// CTA 128x128, 8 warps of 64x32, BK=32, 3-stage cp.async, 2 CTA/SM.
#define BM 128
#define BN 128
#define BK 32
#define ROWB 80
#define T_TILE (128 * ROWB)        /* 10240 */
#define STAGE_B (3 * T_TILE)       /* 30720 */
#define PJ_SMEM (3 * STAGE_B)      /* 92160 -> x2 CTA = 184320 */

#define PROJ_BODY(AP, BhP, BlP)                                                \
    float acc[4][4][4];                                                        \
    _Pragma("unroll")                                                          \
    for (int mi = 0; mi < 4; mi++)                                             \
        _Pragma("unroll")                                                      \
        for (int ni = 0; ni < 4; ni++)                                         \
            _Pragma("unroll")                                                  \
            for (int e = 0; e < 4; e++) acc[mi][ni][e] = 0.0f;                 \
    const int lr = tid >> 2;                                                   \
    const int lch = tid & 3;                                                   \
    const int rowA = (((lane >> 3) & 1) << 3) + (lane & 7);                    \
    const int colA = (lane >> 4) << 3;                                         \
    const int rowB2 = ((lane >> 4) << 3) + (lane & 7);                         \
    const int colB2 = ((lane >> 3) & 1) << 3;                                  \
    auto prefetch = [&](int k0, uint32_t s0) {                                 \
        int ge = k0 + lch * 8;                                                 \
        _Pragma("unroll")                                                      \
        for (int j = 0; j < 2; j++) {                                          \
            int r = lr + j * 64;                                               \
            uint32_t so = (uint32_t)(r * ROWB + lch * 16);                     \
            CP_ASYNC16(s0 + so,              AP + (size_t)(row0 + r) * Cc + ge);  \
            CP_ASYNC16(s0 + T_TILE + so,     BhP + (size_t)(col0 + r) * Cc + ge); \
            CP_ASYNC16(s0 + 2 * T_TILE + so, BlP + (size_t)(col0 + r) * Cc + ge); \
        }                                                                      \
    };                                                                         \
    prefetch(0, sb);                                                           \
    CP_COMMIT();                                                               \
    prefetch(BK, sb + STAGE_B);                                                \
    CP_COMMIT();                                                               \
    int stage = 0;                                                             \
    const int NKst = Cc / BK;                                                  \
    _Pragma("unroll 1")                                                        \
    for (int ks = 0; ks < NKst; ks++) {                                        \
        if (ks + 1 < NKst) { CP_WAIT(1); } else { CP_WAIT(0); }                \
        __syncthreads();                                                       \
        if (ks + 2 < NKst) {                                                   \
            int ns = stage + 2;                                                \
            if (ns >= 3) ns -= 3;                                              \
            prefetch((ks + 2) * BK, sb + ns * STAGE_B);                        \
            CP_COMMIT();                                                       \
        }                                                                      \
        const uint32_t sA = sb + stage * STAGE_B;                              \
        const uint32_t sBh = sA + T_TILE;                                      \
        const uint32_t sBl = sA + 2 * T_TILE;                                  \
        _Pragma("unroll")                                                      \
        for (int kk = 0; kk < 32; kk += 16) {                                  \
            uint32_t a_f[4][4];                                                \
            _Pragma("unroll")                                                  \
            for (int mi = 0; mi < 4; mi++) {                                   \
                uint32_t off = (uint32_t)((wm + mi * 16 + rowA) * ROWB +       \
                                          (kk + colA) * 2);                    \
                LDMATRIX_X4(a_f[mi][0], a_f[mi][1], a_f[mi][2], a_f[mi][3],    \
                            sA + off);                                         \
            }                                                                  \
            uint32_t b_h[4][2], b_l[4][2];                                     \
            _Pragma("unroll")                                                  \
            for (int pr = 0; pr < 2; pr++) {                                   \
                uint32_t off = (uint32_t)((wn + pr * 16 + rowB2) * ROWB +      \
                                          (kk + colB2) * 2);                   \
                LDMATRIX_X4(b_h[2 * pr][0], b_h[2 * pr][1],                    \
                            b_h[2 * pr + 1][0], b_h[2 * pr + 1][1], sBh + off);\
                LDMATRIX_X4(b_l[2 * pr][0], b_l[2 * pr][1],                    \
                            b_l[2 * pr + 1][0], b_l[2 * pr + 1][1], sBl + off);\
            }                                                                  \
            _Pragma("unroll")                                                  \
            for (int mi = 0; mi < 4; mi++)                                     \
                _Pragma("unroll")                                              \
                for (int ni = 0; ni < 4; ni++)                                 \
                    MMA_F16(acc[mi][ni], a_f[mi], b_h[ni]);                    \
            _Pragma("unroll")                                                  \
            for (int mi = 0; mi < 4; mi++)                                     \
                _Pragma("unroll")                                              \
                for (int ni = 0; ni < 4; ni++)                                 \
                    MMA_F16(acc[mi][ni], a_f[mi], b_l[ni]);                    \
        }                                                                      \
        stage++;                                                               \
        if (stage == 3) stage = 0;                                             \
    }

// Merged Q/K/V projection. grid = (Tt/BN, Cc/BM, 6); z = mat*2 + batch.
// Q: plain fp16, pre-scaled by Q2SCALE. K: plain fp16. V: plain fp16 * mask.
__global__ void __launch_bounds__(256, 2) qkv_mma_kernel(
    const float* __restrict__ bq, const float* __restrict__ bk,
    const float* __restrict__ bv)
{
    extern __shared__ char smem[];
    const uint32_t sb = smem_to_u32(smem);
    const int tid = threadIdx.x;
    const int wid = tid >> 5;
    const int lane = tid & 31;
    const int z = blockIdx.z;
    const int b = z & 1;
    const int mat = z >> 1;
    const int row0 = blockIdx.y * BM;
    const int col0 = blockIdx.x * BN;

    const f16* A;
    const float* bias;
    f16* oh;
    float oscale;
    bool domask;
    if (mat == 0)      { A = g_Wq; bias = bq; oh = g_Q; oscale = Q2SCALE; domask = false; }
    else if (mat == 1) { A = g_Wk; bias = bk; oh = g_K; oscale = 1.0f; domask = false; }
    else               { A = g_Wv; bias = bv; oh = g_V; oscale = 1.0f; domask = true; }
    const f16* Bh = g_Xth + (size_t)b * Tt * Cc;
    const f16* Bl = g_Xtl + (size_t)b * Tt * Cc;

    const int wm = (wid >> 2) * 64;
    const int wn = (wid & 3) * 32;

    PROJ_BODY(A, Bh, Bl)

    const int g = lane >> 2;
    const int tig = lane & 3;
#pragma unroll
    for (int mi = 0; mi < 4; mi++) {
#pragma unroll
        for (int part = 0; part < 2; part++) {
            const int o = row0 + wm + mi * 16 + g + part * 8;
            const float bo = bias[o];
#pragma unroll
            for (int ni = 0; ni < 4; ni++) {
#pragma unroll
                for (int e = 0; e < 2; e++) {
                    const int t = col0 + wn + ni * 8 + tig * 2 + e;
                    float v = (acc[mi][ni][part * 2 + e] + bo) * oscale;
                    if (domask) v *= g_maskf[b * Tt + t];
                    size_t idx =
                        (((size_t)b * Hh + (o >> 6)) * Tt + t) * Dd + (o & 63);
                    oh[idx] = __float2half_rn(v);
                }
            }
        }
    }
}

// Output projection: f32 out * mask. grid = (Tt/BN, Cc/BM, Bb).
__global__ void __launch_bounds__(256, 2) projp_mma_kernel(
    const float* __restrict__ bp, float* __restrict__ outf)
{
    extern __shared__ char smem[];
    const uint32_t sb = smem_to_u32(smem);
    const int tid = threadIdx.x;
    const int wid = tid >> 5;
    const int lane = tid & 31;
    const int b = blockIdx.z;
    const int row0 = blockIdx.y * BM;
    const int col0 = blockIdx.x * BN;

    const f16* A = g_Wp;
    const f16* Bh = g_Cth + (size_t)b * Tt * Cc;
    const f16* Bl = g_Ctl + (size_t)b * Tt * Cc;

    const int wm = (wid >> 2) * 64;
    const int wn = (wid & 3) * 32;

    PROJ_BODY(A, Bh, Bl)

    const int g = lane >> 2;
    const int tig = lane & 3;
#pragma unroll
    for (int mi = 0; mi < 4; mi++) {
#pragma unroll
        for (int part = 0; part < 2; part++) {
            const int o = row0 + wm + mi * 16 + g + part * 8;
            const float bo = bp[o];
#pragma unroll
            for (int ni = 0; ni < 4; ni++) {
#pragma unroll
                for (int e = 0; e < 2; e++) {
                    const int t = col0 + wn + ni * 8 + tig * 2 + e;
                    float v = acc[mi][ni][part * 2 + e] + bo;
                    outf[((size_t)b * Cc + o) * Tt + t] = v * g_maskf[b * Tt + t];
                }
            }
        }
    }
}

// ---------------- pure-fp16 flash attention ----------------
// S = Q_f16 * K_f16; O = P_f16 * V_f16 (fp32 accumulate). 128 thr / 128 q-rows,
// m32 warps, 32-key tiles, 2-stage cp.async, ex2 softmax. ctx out: fp16 hi/lo.
#define KST 72
#define AT_TILE (32 * KST * 2)             /* 4608 B per array */
#define AT_STAGE (2 * AT_TILE + 128)       /* 9344 B: K, V + mask */
#define AT_SMEM (2 * AT_STAGE)             /* 18688 B */

__global__ void __launch_bounds__(128, 2) attn_mma_kernel()
{
    extern __shared__ char dynsm[];
    const uint32_t sbase = smem_to_u32(dynsm);

    const int tid = threadIdx.x;
    const int wid = tid >> 5;
    const int lane = tid & 31;
    const int g = lane >> 2;
    const int tig = lane & 3;
    const int bh = blockIdx.y;
    const int b = bh >> 4;
    const int q0 = blockIdx.x * 128;
    const size_t base = (size_t)bh * Tt * Dd;

    const f16* Q = g_Q;
    const f16* K = g_K;
    const f16* V = g_V;
    f16* Ch = g_Cth; f16* Cl = g_Ctl;

    const int rowB = ((lane >> 4) << 3) + (lane & 7);
    const int colB = ((lane >> 3) & 1) << 3;
    const int vrow = (lane & 7) + ((lane >> 3) & 1) * 8;
    const int vcol = (lane >> 4) << 3;

    const int ldrow = tid >> 2;
    const int ldch = tid & 3;

    auto prefetch = [&](int kt, uint32_t st) {
        const char* gk = (const char*)(K + base + (size_t)(kt + ldrow) * Dd);
        const char* gv = (const char*)(V + base + (size_t)(kt + ldrow) * Dd);
        uint32_t so = st + (uint32_t)(ldrow * (KST * 2));
#pragma unroll
        for (int cc = 0; cc < 2; cc++) {
            uint32_t off = (uint32_t)((ldch + cc * 4) * 16);
            CP_ASYNC16(so + off,           gk + off);
            CP_ASYNC16(so + AT_TILE + off, gv + off);
        }
        if (tid < 8) {
            const char* gm = (const char*)(g_maskbias + b * Tt + kt) + tid * 16;
            CP_ASYNC16(st + 2 * AT_TILE + tid * 16, gm);
        }
    };

    uint32_t qf[2][4][4];
#pragma unroll
    for (int mi = 0; mi < 2; mi++) {
        const size_t r0 = base + (size_t)(q0 + wid * 32 + mi * 16 + g) * Dd;
        const size_t r1 = r0 + 8 * Dd;
#pragma unroll
        for (int c = 0; c < 4; c++) {
            int k0 = c * 16 + tig * 2;
            qf[mi][c][0] = *(const uint32_t*)(Q + r0 + k0);
            qf[mi][c][1] = *(const uint32_t*)(Q + r1 + k0);
            qf[mi][c][2] = *(const uint32_t*)(Q + r0 + k0 + 8);
            qf[mi][c][3] = *(const uint32_t*)(Q + r1 + k0 + 8);
        }
    }

    float oacc[2][8][4];
#pragma unroll
    for (int mi = 0; mi < 2; mi++)
#pragma unroll
        for (int j = 0; j < 8; j++)
#pragma unroll
            for (int e = 0; e < 4; e++) oacc[mi][j][e] = 0.0f;
    float mrow[2][2], lrow[2][2];
#pragma unroll
    for (int mi = 0; mi < 2; mi++) {
        mrow[mi][0] = -3.0e38f; mrow[mi][1] = -3.0e38f;
        lrow[mi][0] = 0.0f;     lrow[mi][1] = 0.0f;
    }

    prefetch(0, sbase);
    CP_COMMIT();

    int stage = 0;
#pragma unroll 1
    for (int kt = 0; kt < Tt; kt += 32) {
        CP_WAIT(0);
        __syncthreads();
        if (kt + 32 < Tt) {
            prefetch(kt + 32, sbase + (stage ^ 1) * AT_STAGE);
            CP_COMMIT();
        }

        const uint32_t aK = sbase + stage * AT_STAGE;
        const uint32_t aV = aK + AT_TILE;
        const float* msk = (const float*)(dynsm + stage * AT_STAGE + 2 * AT_TILE);

        // ---- S = Q K^T (single term) ----
        float sacc[2][4][4];
#pragma unroll
        for (int mi = 0; mi < 2; mi++)
#pragma unroll
            for (int j = 0; j < 4; j++)
#pragma unroll
                for (int e = 0; e < 4; e++) sacc[mi][j][e] = 0.0f;

#pragma unroll
        for (int c = 0; c < 4; c++) {
            uint32_t kb[4][2];
#pragma unroll
            for (int pr = 0; pr < 2; pr++) {
                uint32_t off = (uint32_t)(((pr * 16 + rowB) * KST +
                                           c * 16 + colB) * 2);
                LDMATRIX_X4(kb[2 * pr][0], kb[2 * pr][1],
                            kb[2 * pr + 1][0], kb[2 * pr + 1][1], aK + off);
            }
#pragma unroll
            for (int mi = 0; mi < 2; mi++)
#pragma unroll
                for (int j = 0; j < 4; j++)
                    MMA_F16(sacc[mi][j], qf[mi][c], kb[j]);
        }

        // ---- additive mask + online softmax (ex2 domain) ----
        float al[2][2];
#pragma unroll
        for (int mi = 0; mi < 2; mi++) {
            float mx0 = -3.0e38f, mx1 = -3.0e38f;
#pragma unroll
            for (int j = 0; j < 4; j++) {
                float mb0 = msk[j * 8 + tig * 2];
                float mb1 = msk[j * 8 + tig * 2 + 1];
                float s0 = sacc[mi][j][0] + mb0;
                float s1 = sacc[mi][j][1] + mb1;
                float s2 = sacc[mi][j][2] + mb0;
                float s3 = sacc[mi][j][3] + mb1;
                sacc[mi][j][0] = s0; sacc[mi][j][1] = s1;
                sacc[mi][j][2] = s2; sacc[mi][j][3] = s3;
                mx0 = fmaxf(mx0, fmaxf(s0, s1));
                mx1 = fmaxf(mx1, fmaxf(s2, s3));
            }
            mx0 = fmaxf(mx0, __shfl_xor_sync(0xffffffffu, mx0, 1));
            mx0 = fmaxf(mx0, __shfl_xor_sync(0xffffffffu, mx0, 2));
            mx1 = fmaxf(mx1, __shfl_xor_sync(0xffffffffu, mx1, 1));
            mx1 = fmaxf(mx1, __shfl_xor_sync(0xffffffffu, mx1, 2));
            float mn0 = fmaxf(mrow[mi][0], mx0);
            float mn1 = fmaxf(mrow[mi][1], mx1);
            float sum0 = 0.0f, sum1 = 0.0f;
#pragma unroll
            for (int j = 0; j < 4; j++) {
                float p0 = ex2(sacc[mi][j][0] - mn0);
                float p1 = ex2(sacc[mi][j][1] - mn0);
                float p2 = ex2(sacc[mi][j][2] - mn1);
                float p3 = ex2(sacc[mi][j][3] - mn1);
                sacc[mi][j][0] = p0; sacc[mi][j][1] = p1;
                sacc[mi][j][2] = p2; sacc[mi][j][3] = p3;
                sum0 += p0 + p1;
                sum1 += p2 + p3;
            }
            sum0 += __shfl_xor_sync(0xffffffffu, sum0, 1);
            sum0 += __shfl_xor_sync(0xffffffffu, sum0, 2);
            sum1 += __shfl_xor_sync(0xffffffffu, sum1, 1);
            sum1 += __shfl_xor_sync(0xffffffffu, sum1, 2);
            float a0 = ex2(mrow[mi][0] - mn0);
            float a1 = ex2(mrow[mi][1] - mn1);
            lrow[mi][0] = lrow[mi][0] * a0 + sum0;
            lrow[mi][1] = lrow[mi][1] * a1 + sum1;
            mrow[mi][0] = mn0;
            mrow[mi][1] = mn1;
            al[mi][0] = a0;
            al[mi][1] = a1;
        }
#pragma unroll
        for (int mi = 0; mi < 2; mi++)
#pragma unroll
            for (int j = 0; j < 8; j++) {
                oacc[mi][j][0] *= al[mi][0]; oacc[mi][j][1] *= al[mi][0];
                oacc[mi][j][2] *= al[mi][1]; oacc[mi][j][3] *= al[mi][1];
            }

        // ---- O += P_f16 V_f16 (single term) ----
#pragma unroll
        for (int kc = 0; kc < 2; kc++) {
            uint32_t vb[8][2];
#pragma unroll
            for (int ng = 0; ng < 4; ng++) {
                uint32_t off = (uint32_t)(((kc * 16 + vrow) * KST +
                                           ng * 16 + vcol) * 2);
                LDMATRIX_X4T(vb[2 * ng][0], vb[2 * ng][1],
                             vb[2 * ng + 1][0], vb[2 * ng + 1][1], aV + off);
            }
            uint32_t paf[2][4];
#pragma unroll
            for (int mi = 0; mi < 2; mi++) {
                paf[mi][0] = pack_h2(sacc[mi][2 * kc][0], sacc[mi][2 * kc][1]);
                paf[mi][1] = pack_h2(sacc[mi][2 * kc][2], sacc[mi][2 * kc][3]);
                paf[mi][2] = pack_h2(sacc[mi][2 * kc + 1][0], sacc[mi][2 * kc + 1][1]);
                paf[mi][3] = pack_h2(sacc[mi][2 * kc + 1][2], sacc[mi][2 * kc + 1][3]);
            }
#pragma unroll
            for (int mi = 0; mi < 2; mi++)
#pragma unroll
                for (int j = 0; j < 8; j++)
                    MMA_F16(oacc[mi][j], paf[mi], vb[j]);
        }
        stage ^= 1;
    }

    // ---- epilogue: ctx[b][t][c] fp16 hi/lo ----
    const int cb = (bh & 15) * 64;
#pragma unroll
    for (int mi = 0; mi < 2; mi++) {
        const float inv0 = 1.0f / lrow[mi][0];
        const float inv1 = 1.0f / lrow[mi][1];
        const int t0 = q0 + wid * 32 + mi * 16 + g;
        const size_t o0 = ((size_t)b * Tt + t0) * Cc + cb;
        const size_t o1 = o0 + 8 * Cc;
#pragma unroll
        for (int j = 0; j < 8; j++) {
            int cc = j * 8 + tig * 2;
            float v0 = oacc[mi][j][0] * inv0, v1 = oacc[mi][j][1] * inv0;
            float v2 = oacc[mi][j][2] * inv1, v3 = oacc[mi][j][3] * inv1;
            float h0 = __half2float(__float2half_rn(v0));
            float h1 = __half2float(__float2half_rn(v1));
            float h2 = __half2float(__float2half_rn(v2));
            float h3 = __half2float(__float2half_rn(v3));
            *(uint32_t*)(Ch + o0 + cc) = pack_h2(v0, v1);
            *(uint32_t*)(Cl + o0 + cc) = pack_h2(v0 - h0, v1 - h1);
            *(uint32_t*)(Ch + o1 + cc) = pack_h2(v2, v3);
            *(uint32_t*)(Cl + o1 + cc) = pack_h2(v2 - h2, v3 - h3);
        }
    }
}

// ---------------- mask echo (second tuple output) ----------------
__global__ void mask_out_kernel(float* __restrict__ out) {
    int i = blockIdx.x * blockDim.x + threadIdx.x;
    if (i < Bb * Tt) out[i] = g_maskf[i];
}

// ---------------- launch ----------------
extern "C" void kernel_launch(void* const* d_in, const int* in_sizes, int n_in,
                              void* d_out, int out_size)
{
    const float* x  = (const float*)d_in[0];
    const void*  mk = d_in[1];
    const float* Wq = (const float*)d_in[2];
    const float* bq = (const float*)d_in[3];
    const float* Wk = (const float*)d_in[4];
    const float* bk = (const float*)d_in[5];
    const float* Wv = (const float*)d_in[6];
    const float* bv = (const float*)d_in[7];
    const float* Wp = (const float*)d_in[8];
    const float* bp = (const float*)d_in[9];
    float* out = (float*)d_out;

    f16 *xth, *xtl;
    cudaGetSymbolAddress((void**)&xth, g_Xth);
    cudaGetSymbolAddress((void**)&xtl, g_Xtl);

    cudaFuncSetAttribute(qkv_mma_kernel,
                         cudaFuncAttributeMaxDynamicSharedMemorySize, PJ_SMEM);
    cudaFuncSetAttribute(projp_mma_kernel,
                         cudaFuncAttributeMaxDynamicSharedMemorySize, PJ_SMEM);
    cudaFuncSetAttribute(attn_mma_kernel,
                         cudaFuncAttributeMaxDynamicSharedMemorySize, AT_SMEM);

    mask_convert_kernel<<<1, 256>>>(mk);

    convw4_kernel<<<dim3(Cc * Cc / 1024, 4), 256>>>(Wq, Wk, Wv, Wp);
    convT_kernel<<<dim3(Tt / 32, Cc / 32, Bb), dim3(32, 8)>>>(x, xth, xtl);

    qkv_mma_kernel<<<dim3(Tt / BN, Cc / BM, 6), 256, PJ_SMEM>>>(bq, bk, bv);

    attn_mma_kernel<<<dim3(Tt / 128, Bb * Hh), 128, AT_SMEM>>>();

    projp_mma_kernel<<<dim3(Tt / BN, Cc / BM, Bb), 256, PJ_SMEM>>>(bp, out);

    if (out_size >= Bb * Cc * Tt + Bb * Tt) {
        mask_out_kernel<<<(Bb * Tt + 255) / 256, 256>>>(out + (size_t)Bb * Cc * Tt);
    }
}

// round 16
// speedup vs baseline: 1.6166x; 1.3211x over previous
#include <cuda_runtime.h>
#include <cuda_fp16.h>
#include <cstdint>
#include <math.h>

#define Bb 2
#define Cc 1024
#define Tt 2048
#define Hh 16
#define Dd 64
/* exp2-domain scale: 1/sqrt(64) * log2(e) */
#define Q2SCALE 0.18033688011112042f

typedef __half f16;

// ---------------- scratch (device globals: allocation-free) ----------------
__device__ float g_maskf[Bb * Tt];
__device__ float g_maskbias[Bb * Tt];
__device__ f16 g_Wq[Cc * Cc], g_Wk[Cc * Cc], g_Wv[Cc * Cc], g_Wp[Cc * Cc];
__device__ f16 g_Xt[(size_t)Bb * Tt * Cc];
__device__ f16 g_Q[(size_t)Bb * Hh * Tt * Dd];
__device__ f16 g_K[(size_t)Bb * Hh * Tt * Dd];
__device__ f16 g_V[(size_t)Bb * Hh * Tt * Dd];
__device__ f16 g_Ct[(size_t)Bb * Tt * Cc];

// ======================= helpers =======================
__device__ __forceinline__ uint32_t smem_to_u32(const void* p) {
    uint32_t a;
    asm("{ .reg .u64 t; cvta.to.shared.u64 t, %1; cvt.u32.u64 %0, t; }"
        : "=r"(a) : "l"(p));
    return a;
}
__device__ __forceinline__ float ex2(float x) {
    float r;
    asm("ex2.approx.f32 %0, %1;" : "=f"(r) : "f"(x));
    return r;
}
#define CP_ASYNC16(saddr, gptr) \
    asm volatile("cp.async.cg.shared.global [%0], [%1], 16;" \
        :: "r"(saddr), "l"(gptr) : "memory")
#define CP_COMMIT() asm volatile("cp.async.commit_group;" ::: "memory")
#define CP_WAIT(N)  asm volatile("cp.async.wait_group %0;" :: "n"(N) : "memory")
#define LDMATRIX_X4(r0, r1, r2, r3, addr) \
    asm volatile("ldmatrix.sync.aligned.m8n8.x4.shared.b16 {%0,%1,%2,%3}, [%4];" \
        : "=r"(r0), "=r"(r1), "=r"(r2), "=r"(r3) : "r"(addr))
#define LDMATRIX_X4T(r0, r1, r2, r3, addr) \
    asm volatile("ldmatrix.sync.aligned.m8n8.x4.trans.shared.b16 {%0,%1,%2,%3}, [%4];" \
        : "=r"(r0), "=r"(r1), "=r"(r2), "=r"(r3) : "r"(addr))
#define MMA_F16(c, a, b) \
    asm volatile("mma.sync.aligned.m16n8k16.row.col.f32.f16.f16.f32 " \
        "{%0,%1,%2,%3}, {%4,%5,%6,%7}, {%8,%9}, {%0,%1,%2,%3};" \
        : "+f"((c)[0]), "+f"((c)[1]), "+f"((c)[2]), "+f"((c)[3]) \
        : "r"((a)[0]), "r"((a)[1]), "r"((a)[2]), "r"((a)[3]), \
          "r"((b)[0]), "r"((b)[1]))

__device__ __forceinline__ uint32_t pack_h2(float x, float y) {
    __half2 t = __floats2half2_rn(x, y);
    return *(uint32_t*)&t;
}

// ---------------- mask normalization ----------------
__global__ void mask_convert_kernel(const void* __restrict__ mraw) {
    const int tid = threadIdx.x;
    bool isf = true, isi = true;
    const float* f = (const float*)mraw;
    const int* w = (const int*)mraw;
    for (int i = tid; i < Bb * Tt / 4; i += 256) {
        float v = f[i];
        if (!(v == 0.0f || v == 1.0f)) isf = false;
        int iv = w[i];
        if (!(iv == 0 || iv == 1)) isi = false;
    }
    int allf = __syncthreads_and(isf ? 1 : 0);
    int alli = __syncthreads_and(isi ? 1 : 0);
    int fmt = allf ? 0 : (alli ? 1 : 2);
    for (int i = tid; i < Bb * Tt; i += 256) {
        float v;
        if (fmt == 0)      v = ((const float*)mraw)[i];
        else if (fmt == 1) v = (float)((const int*)mraw)[i];
        else               v = (float)((const unsigned char*)mraw)[i];
        bool on = (v != 0.0f);
        g_maskf[i] = on ? 1.0f : 0.0f;
        g_maskbias[i] = on ? 0.0f : -1e30f;
    }
}

// ---------------- conversions ----------------
__global__ void convw4_kernel(
    const float* __restrict__ s0, const float* __restrict__ s1,
    const float* __restrict__ s2, const float* __restrict__ s3)
{
    const float* s;
    f16* h;
    switch (blockIdx.y) {
        case 0:  s = s0; h = g_Wq; break;
        case 1:  s = s1; h = g_Wk; break;
        case 2:  s = s2; h = g_Wv; break;
        default: s = s3; h = g_Wp; break;
    }
    int i = (blockIdx.x * 256 + threadIdx.x) * 4;
    float4 v = *(const float4*)(s + i);
    uint2 ho;
    ho.x = pack_h2(v.x, v.y);
    ho.y = pack_h2(v.z, v.w);
    *(uint2*)(h + i) = ho;
}

// src [b][C][T] f32 -> dst [b][T][C] plain fp16 (transpose)
__global__ void convT_kernel(const float* __restrict__ src,
                             f16* __restrict__ dh) {
    __shared__ float tile[32][33];
    const int b = blockIdx.z;
    const int t0 = blockIdx.x * 32;
    const int c0 = blockIdx.y * 32;
    const float* s = src + (size_t)b * Cc * Tt;
    f16* oh = dh + (size_t)b * Tt * Cc;
    const int tx = threadIdx.x;
    const int ty = threadIdx.y;
#pragma unroll
    for (int i = ty; i < 32; i += 8)
        tile[i][tx] = s[(size_t)(c0 + i) * Tt + t0 + tx];
    __syncthreads();
#pragma unroll
    for (int i = ty; i < 32; i += 8) {
        float v = tile[tx][i];
        oh[(size_t)(t0 + i) * Cc + c0 + tx] = __float2half_rn(v);
    }
}

// ---------------- pure-fp16 projection GEMMs ----------------
// A = W fp16 [o][c]; B = X^T fp16 [t][c]. Single MMA term, fp32 accumulate.
// CTA 128x128, 8 warps of 64x32, BK=32, 3-stage cp.async, 2 CTA/SM.
#define BM 128
#define BN 128
#define BK 32
#define ROWB 80
#define T_TILE (128 * ROWB)        /* 10240 */
#define STAGE_B (2 * T_TILE)       /* 20480 */
#define PJ_SMEM (3 * STAGE_B)      /* 61440 -> x2 CTA = 122880 */

#define PROJ_BODY(AP, BP)                                                      \
    float acc[4][4][4];                                                        \
    _Pragma("unroll")                                                          \
    for (int mi = 0; mi < 4; mi++)                                             \
        _Pragma("unroll")                                                      \
        for (int ni = 0; ni < 4; ni++)                                         \
            _Pragma("unroll")                                                  \
            for (int e = 0; e < 4; e++) acc[mi][ni][e] = 0.0f;                 \
    const int lr = tid >> 2;                                                   \
    const int lch = tid & 3;                                                   \
    const int rowA = (((lane >> 3) & 1) << 3) + (lane & 7);                    \
    const int colA = (lane >> 4) << 3;                                         \
    const int rowB2 = ((lane >> 4) << 3) + (lane & 7);                         \
    const int colB2 = ((lane >> 3) & 1) << 3;                                  \
    auto prefetch = [&](int k0, uint32_t s0) {                                 \
        int ge = k0 + lch * 8;                                                 \
        _Pragma("unroll")                                                      \
        for (int j = 0; j < 2; j++) {                                          \
            int r = lr + j * 64;                                               \
            uint32_t so = (uint32_t)(r * ROWB + lch * 16);                     \
            CP_ASYNC16(s0 + so,          AP + (size_t)(row0 + r) * Cc + ge);   \
            CP_ASYNC16(s0 + T_TILE + so, BP + (size_t)(col0 + r) * Cc + ge);   \
        }                                                                      \
    };                                                                         \
    prefetch(0, sb);                                                           \
    CP_COMMIT();                                                               \
    prefetch(BK, sb + STAGE_B);                                                \
    CP_COMMIT();                                                               \
    int stage = 0;                                                             \
    const int NKst = Cc / BK;                                                  \
    _Pragma("unroll 1")                                                        \
    for (int ks = 0; ks < NKst; ks++) {                                        \
        if (ks + 1 < NKst) { CP_WAIT(1); } else { CP_WAIT(0); }                \
        __syncthreads();                                                       \
        if (ks + 2 < NKst) {                                                   \
            int ns = stage + 2;                                                \
            if (ns >= 3) ns -= 3;                                              \
            prefetch((ks + 2) * BK, sb + ns * STAGE_B);                        \
            CP_COMMIT();                                                       \
        }                                                                      \
        const uint32_t sA = sb + stage * STAGE_B;                              \
        const uint32_t sB = sA + T_TILE;                                       \
        _Pragma("unroll")                                                      \
        for (int kk = 0; kk < 32; kk += 16) {                                  \
            uint32_t a_f[4][4];                                                \
            _Pragma("unroll")                                                  \
            for (int mi = 0; mi < 4; mi++) {                                   \
                uint32_t off = (uint32_t)((wm + mi * 16 + rowA) * ROWB +       \
                                          (kk + colA) * 2);                    \
                LDMATRIX_X4(a_f[mi][0], a_f[mi][1], a_f[mi][2], a_f[mi][3],    \
                            sA + off);                                         \
            }                                                                  \
            uint32_t b_f[4][2];                                                \
            _Pragma("unroll")                                                  \
            for (int pr = 0; pr < 2; pr++) {                                   \
                uint32_t off = (uint32_t)((wn + pr * 16 + rowB2) * ROWB +      \
                                          (kk + colB2) * 2);                   \
                LDMATRIX_X4(b_f[2 * pr][0], b_f[2 * pr][1],                    \
                            b_f[2 * pr + 1][0], b_f[2 * pr + 1][1], sB + off); \
            }                                                                  \
            _Pragma("unroll")                                                  \
            for (int mi = 0; mi < 4; mi++)                                     \
                _Pragma("unroll")                                              \
                for (int ni = 0; ni < 4; ni++)                                 \
                    MMA_F16(acc[mi][ni], a_f[mi], b_f[ni]);                    \
        }                                                                      \
        stage++;                                                               \
        if (stage == 3) stage = 0;                                             \
    }

// Merged Q/K/V projection. grid = (Tt/BN, Cc/BM, 6); z = mat*2 + batch.
__global__ void __launch_bounds__(256, 2) qkv_mma_kernel(
    const float* __restrict__ bq, const float* __restrict__ bk,
    const float* __restrict__ bv)
{
    extern __shared__ char smem[];
    const uint32_t sb = smem_to_u32(smem);
    const int tid = threadIdx.x;
    const int wid = tid >> 5;
    const int lane = tid & 31;
    const int z = blockIdx.z;
    const int b = z & 1;
    const int mat = z >> 1;
    const int row0 = blockIdx.y * BM;
    const int col0 = blockIdx.x * BN;

    const f16* A;
    const float* bias;
    f16* oh;
    float oscale;
    bool domask;
    if (mat == 0)      { A = g_Wq; bias = bq; oh = g_Q; oscale = Q2SCALE; domask = false; }
    else if (mat == 1) { A = g_Wk; bias = bk; oh = g_K; oscale = 1.0f; domask = false; }
    else               { A = g_Wv; bias = bv; oh = g_V; oscale = 1.0f; domask = true; }
    const f16* Bx = g_Xt + (size_t)b * Tt * Cc;

    const int wm = (wid >> 2) * 64;
    const int wn = (wid & 3) * 32;

    PROJ_BODY(A, Bx)

    const int g = lane >> 2;
    const int tig = lane & 3;
#pragma unroll
    for (int mi = 0; mi < 4; mi++) {
#pragma unroll
        for (int part = 0; part < 2; part++) {
            const int o = row0 + wm + mi * 16 + g + part * 8;
            const float bo = bias[o];
#pragma unroll
            for (int ni = 0; ni < 4; ni++) {
#pragma unroll
                for (int e = 0; e < 2; e++) {
                    const int t = col0 + wn + ni * 8 + tig * 2 + e;
                    float v = (acc[mi][ni][part * 2 + e] + bo) * oscale;
                    if (domask) v *= g_maskf[b * Tt + t];
                    size_t idx =
                        (((size_t)b * Hh + (o >> 6)) * Tt + t) * Dd + (o & 63);
                    oh[idx] = __float2half_rn(v);
                }
            }
        }
    }
}

// Output projection: f32 out * mask. grid = (Tt/BN, Cc/BM, Bb).
__global__ void __launch_bounds__(256, 2) projp_mma_kernel(
    const float* __restrict__ bp, float* __restrict__ outf)
{
    extern __shared__ char smem[];
    const uint32_t sb = smem_to_u32(smem);
    const int tid = threadIdx.x;
    const int wid = tid >> 5;
    const int lane = tid & 31;
    const int b = blockIdx.z;
    const int row0 = blockIdx.y * BM;
    const int col0 = blockIdx.x * BN;

    const f16* A = g_Wp;
    const f16* Bx = g_Ct + (size_t)b * Tt * Cc;

    const int wm = (wid >> 2) * 64;
    const int wn = (wid & 3) * 32;

    PROJ_BODY(A, Bx)

    const int g = lane >> 2;
    const int tig = lane & 3;
#pragma unroll
    for (int mi = 0; mi < 4; mi++) {
#pragma unroll
        for (int part = 0; part < 2; part++) {
            const int o = row0 + wm + mi * 16 + g + part * 8;
            const float bo = bp[o];
#pragma unroll
            for (int ni = 0; ni < 4; ni++) {
#pragma unroll
                for (int e = 0; e < 2; e++) {
                    const int t = col0 + wn + ni * 8 + tig * 2 + e;
                    float v = acc[mi][ni][part * 2 + e] + bo;
                    outf[((size_t)b * Cc + o) * Tt + t] = v * g_maskf[b * Tt + t];
                }
            }
        }
    }
}

// ---------------- pure-fp16 flash attention ----------------
// S = Q K; O = P V (fp32 accumulate). 128 thr / 128 q-rows, m32 warps,
// 32-key tiles, 2-stage cp.async, ex2 softmax. ctx out: plain fp16.
#define KST 72
#define AT_TILE (32 * KST * 2)             /* 4608 B per array */
#define AT_STAGE (2 * AT_TILE + 128)       /* 9344 B: K, V + mask */
#define AT_SMEM (2 * AT_STAGE)             /* 18688 B */

__global__ void __launch_bounds__(128, 2) attn_mma_kernel()
{
    extern __shared__ char dynsm[];
    const uint32_t sbase = smem_to_u32(dynsm);

    const int tid = threadIdx.x;
    const int wid = tid >> 5;
    const int lane = tid & 31;
    const int g = lane >> 2;
    const int tig = lane & 3;
    const int bh = blockIdx.y;
    const int b = bh >> 4;
    const int q0 = blockIdx.x * 128;
    const size_t base = (size_t)bh * Tt * Dd;

    const f16* Q = g_Q;
    const f16* K = g_K;
    const f16* V = g_V;
    f16* Ct = g_Ct;

    const int rowB = ((lane >> 4) << 3) + (lane & 7);
    const int colB = ((lane >> 3) & 1) << 3;
    const int vrow = (lane & 7) + ((lane >> 3) & 1) * 8;
    const int vcol = (lane >> 4) << 3;

    const int ldrow = tid >> 2;
    const int ldch = tid & 3;

    auto prefetch = [&](int kt, uint32_t st) {
        const char* gk = (const char*)(K + base + (size_t)(kt + ldrow) * Dd);
        const char* gv = (const char*)(V + base + (size_t)(kt + ldrow) * Dd);
        uint32_t so = st + (uint32_t)(ldrow * (KST * 2));
#pragma unroll
        for (int cc = 0; cc < 2; cc++) {
            uint32_t off = (uint32_t)((ldch + cc * 4) * 16);
            CP_ASYNC16(so + off,           gk + off);
            CP_ASYNC16(so + AT_TILE + off, gv + off);
        }
        if (tid < 8) {
            const char* gm = (const char*)(g_maskbias + b * Tt + kt) + tid * 16;
            CP_ASYNC16(st + 2 * AT_TILE + tid * 16, gm);
        }
    };

    uint32_t qf[2][4][4];
#pragma unroll
    for (int mi = 0; mi < 2; mi++) {
        const size_t r0 = base + (size_t)(q0 + wid * 32 + mi * 16 + g) * Dd;
        const size_t r1 = r0 + 8 * Dd;
#pragma unroll
        for (int c = 0; c < 4; c++) {
            int k0 = c * 16 + tig * 2;
            qf[mi][c][0] = *(const uint32_t*)(Q + r0 + k0);
            qf[mi][c][1] = *(const uint32_t*)(Q + r1 + k0);
            qf[mi][c][2] = *(const uint32_t*)(Q + r0 + k0 + 8);
            qf[mi][c][3] = *(const uint32_t*)(Q + r1 + k0 + 8);
        }
    }

    float oacc[2][8][4];
#pragma unroll
    for (int mi = 0; mi < 2; mi++)
#pragma unroll
        for (int j = 0; j < 8; j++)
#pragma unroll
            for (int e = 0; e < 4; e++) oacc[mi][j][e] = 0.0f;
    float mrow[2][2], lrow[2][2];
#pragma unroll
    for (int mi = 0; mi < 2; mi++) {
        mrow[mi][0] = -3.0e38f; mrow[mi][1] = -3.0e38f;
        lrow[mi][0] = 0.0f;     lrow[mi][1] = 0.0f;
    }

    prefetch(0, sbase);
    CP_COMMIT();

    int stage = 0;
#pragma unroll 1
    for (int kt = 0; kt < Tt; kt += 32) {
        CP_WAIT(0);
        __syncthreads();
        if (kt + 32 < Tt) {
            prefetch(kt + 32, sbase + (stage ^ 1) * AT_STAGE);
            CP_COMMIT();
        }

        const uint32_t aK = sbase + stage * AT_STAGE;
        const uint32_t aV = aK + AT_TILE;
        const float* msk = (const float*)(dynsm + stage * AT_STAGE + 2 * AT_TILE);

        float sacc[2][4][4];
#pragma unroll
        for (int mi = 0; mi < 2; mi++)
#pragma unroll
            for (int j = 0; j < 4; j++)
#pragma unroll
                for (int e = 0; e < 4; e++) sacc[mi][j][e] = 0.0f;

#pragma unroll
        for (int c = 0; c < 4; c++) {
            uint32_t kb[4][2];
#pragma unroll
            for (int pr = 0; pr < 2; pr++) {
                uint32_t off = (uint32_t)(((pr * 16 + rowB) * KST +
                                           c * 16 + colB) * 2);
                LDMATRIX_X4(kb[2 * pr][0], kb[2 * pr][1],
                            kb[2 * pr + 1][0], kb[2 * pr + 1][1], aK + off);
            }
#pragma unroll
            for (int mi = 0; mi < 2; mi++)
#pragma unroll
                for (int j = 0; j < 4; j++)
                    MMA_F16(sacc[mi][j], qf[mi][c], kb[j]);
        }

        float al[2][2];
#pragma unroll
        for (int mi = 0; mi < 2; mi++) {
            float mx0 = -3.0e38f, mx1 = -3.0e38f;
#pragma unroll
            for (int j = 0; j < 4; j++) {
                float mb0 = msk[j * 8 + tig * 2];
                float mb1 = msk[j * 8 + tig * 2 + 1];
                float s0 = sacc[mi][j][0] + mb0;
                float s1 = sacc[mi][j][1] + mb1;
                float s2 = sacc[mi][j][2] + mb0;
                float s3 = sacc[mi][j][3] + mb1;
                sacc[mi][j][0] = s0; sacc[mi][j][1] = s1;
                sacc[mi][j][2] = s2; sacc[mi][j][3] = s3;
                mx0 = fmaxf(mx0, fmaxf(s0, s1));
                mx1 = fmaxf(mx1, fmaxf(s2, s3));
            }
            mx0 = fmaxf(mx0, __shfl_xor_sync(0xffffffffu, mx0, 1));
            mx0 = fmaxf(mx0, __shfl_xor_sync(0xffffffffu, mx0, 2));
            mx1 = fmaxf(mx1, __shfl_xor_sync(0xffffffffu, mx1, 1));
            mx1 = fmaxf(mx1, __shfl_xor_sync(0xffffffffu, mx1, 2));
            float mn0 = fmaxf(mrow[mi][0], mx0);
            float mn1 = fmaxf(mrow[mi][1], mx1);
            float sum0 = 0.0f, sum1 = 0.0f;
#pragma unroll
            for (int j = 0; j < 4; j++) {
                float p0 = ex2(sacc[mi][j][0] - mn0);
                float p1 = ex2(sacc[mi][j][1] - mn0);
                float p2 = ex2(sacc[mi][j][2] - mn1);
                float p3 = ex2(sacc[mi][j][3] - mn1);
                sacc[mi][j][0] = p0; sacc[mi][j][1] = p1;
                sacc[mi][j][2] = p2; sacc[mi][j][3] = p3;
                sum0 += p0 + p1;
                sum1 += p2 + p3;
            }
            sum0 += __shfl_xor_sync(0xffffffffu, sum0, 1);
            sum0 += __shfl_xor_sync(0xffffffffu, sum0, 2);
            sum1 += __shfl_xor_sync(0xffffffffu, sum1, 1);
            sum1 += __shfl_xor_sync(0xffffffffu, sum1, 2);
            float a0 = ex2(mrow[mi][0] - mn0);
            float a1 = ex2(mrow[mi][1] - mn1);
            lrow[mi][0] = lrow[mi][0] * a0 + sum0;
            lrow[mi][1] = lrow[mi][1] * a1 + sum1;
            mrow[mi][0] = mn0;
            mrow[mi][1] = mn1;
            al[mi][0] = a0;
            al[mi][1] = a1;
        }
#pragma unroll
        for (int mi = 0; mi < 2; mi++)
#pragma unroll
            for (int j = 0; j < 8; j++) {
                oacc[mi][j][0] *= al[mi][0]; oacc[mi][j][1] *= al[mi][0];
                oacc[mi][j][2] *= al[mi][1]; oacc[mi][j][3] *= al[mi][1];
            }

#pragma unroll
        for (int kc = 0; kc < 2; kc++) {
            uint32_t vb[8][2];
#pragma unroll
            for (int ng = 0; ng < 4; ng++) {
                uint32_t off = (uint32_t)(((kc * 16 + vrow) * KST +
                                           ng * 16 + vcol) * 2);
                LDMATRIX_X4T(vb[2 * ng][0], vb[2 * ng][1],
                             vb[2 * ng + 1][0], vb[2 * ng + 1][1], aV + off);
            }
            uint32_t paf[2][4];
#pragma unroll
            for (int mi = 0; mi < 2; mi++) {
                paf[mi][0] = pack_h2(sacc[mi][2 * kc][0], sacc[mi][2 * kc][1]);
                paf[mi][1] = pack_h2(sacc[mi][2 * kc][2], sacc[mi][2 * kc][3]);
                paf[mi][2] = pack_h2(sacc[mi][2 * kc + 1][0], sacc[mi][2 * kc + 1][1]);
                paf[mi][3] = pack_h2(sacc[mi][2 * kc + 1][2], sacc[mi][2 * kc + 1][3]);
            }
#pragma unroll
            for (int mi = 0; mi < 2; mi++)
#pragma unroll
                for (int j = 0; j < 8; j++)
                    MMA_F16(oacc[mi][j], paf[mi], vb[j]);
        }
        stage ^= 1;
    }

    // ---- epilogue: ctx[b][t][c] plain fp16 ----
    const int cb = (bh & 15) * 64;
#pragma unroll
    for (int mi = 0; mi < 2; mi++) {
        const float inv0 = 1.0f / lrow[mi][0];
        const float inv1 = 1.0f / lrow[mi][1];
        const int t0 = q0 + wid * 32 + mi * 16 + g;
        const size_t o0 = ((size_t)b * Tt + t0) * Cc + cb;
        const size_t o1 = o0 + 8 * Cc;
#pragma unroll
        for (int j = 0; j < 8; j++) {
            int cc = j * 8 + tig * 2;
            *(uint32_t*)(Ct + o0 + cc) =
                pack_h2(oacc[mi][j][0] * inv0, oacc[mi][j][1] * inv0);
            *(uint32_t*)(Ct + o1 + cc) =
                pack_h2(oacc[mi][j][2] * inv1, oacc[mi][j][3] * inv1);
        }
    }
}

// ---------------- mask echo (second tuple output) ----------------
__global__ void mask_out_kernel(float* __restrict__ out) {
    int i = blockIdx.x * blockDim.x + threadIdx.x;
    if (i < Bb * Tt) out[i] = g_maskf[i];
}

// ---------------- launch ----------------
extern "C" void kernel_launch(void* const* d_in, const int* in_sizes, int n_in,
                              void* d_out, int out_size)
{
    const float* x  = (const float*)d_in[0];
    const void*  mk = d_in[1];
    const float* Wq = (const float*)d_in[2];
    const float* bq = (const float*)d_in[3];
    const float* Wk = (const float*)d_in[4];
    const float* bk = (const float*)d_in[5];
    const float* Wv = (const float*)d_in[6];
    const float* bv = (const float*)d_in[7];
    const float* Wp = (const float*)d_in[8];
    const float* bp = (const float*)d_in[9];
    float* out = (float*)d_out;

    f16* xt;
    cudaGetSymbolAddress((void**)&xt, g_Xt);

    cudaFuncSetAttribute(qkv_mma_kernel,
                         cudaFuncAttributeMaxDynamicSharedMemorySize, PJ_SMEM);
    cudaFuncSetAttribute(projp_mma_kernel,
                         cudaFuncAttributeMaxDynamicSharedMemorySize, PJ_SMEM);
    cudaFuncSetAttribute(attn_mma_kernel,
                         cudaFuncAttributeMaxDynamicSharedMemorySize, AT_SMEM);

    mask_convert_kernel<<<1, 256>>>(mk);

    convw4_kernel<<<dim3(Cc * Cc / 1024, 4), 256>>>(Wq, Wk, Wv, Wp);
    convT_kernel<<<dim3(Tt / 32, Cc / 32, Bb), dim3(32, 8)>>>(x, xt);

    qkv_mma_kernel<<<dim3(Tt / BN, Cc / BM, 6), 256, PJ_SMEM>>>(bq, bk, bv);

    attn_mma_kernel<<<dim3(Tt / 128, Bb * Hh), 128, AT_SMEM>>>();

    projp_mma_kernel<<<dim3(Tt / BN, Cc / BM, Bb), 256, PJ_SMEM>>>(bp, out);

    if (out_size >= Bb * Cc * Tt + Bb * Tt) {
        mask_out_kernel<<<(Bb * Tt + 255) / 256, 256>>>(out + (size_t)Bb * Cc * Tt);
    }
}